// round 17
// baseline (speedup 1.0000x reference)
#include <cuda_runtime.h>

typedef unsigned long long ULL;

#define NB  2
#define SEQ 512
#define HD  256

// Scratch (allocation-free):
//   g_dprojT[b][d][q] = |w_d|*(dec_proj + bm_d)   (TRANSPOSED)
//   g_eprojT[b][d][e] = |w_d|*enc_proj
__device__ float g_dprojT[NB*HD*SEQ];
__device__ float g_eprojT[NB*HD*SEQ];

__device__ __forceinline__ ULL add2(ULL a, ULL b) {
    ULL r; asm("add.rn.f32x2 %0,%1,%2;" : "=l"(r) : "l"(a), "l"(b)); return r;
}
__device__ __forceinline__ ULL fma2(ULL a, ULL b, ULL c) {
    ULL r; asm("fma.rn.f32x2 %0,%1,%2,%3;" : "=l"(r) : "l"(a), "l"(b), "l"(c)); return r;
}
__device__ __forceinline__ float f_lo(ULL a) { return __uint_as_float((unsigned)a); }
__device__ __forceinline__ float f_hi(ULL a) { return __uint_as_float((unsigned)(a >> 32)); }
__device__ __forceinline__ ULL pack2(float lo, float hi) {
    ULL r; asm("mov.b64 %0,{%1,%2};" : "=l"(r) : "f"(lo), "f"(hi)); return r;
}
// packed relu: max(s,0) per 32-bit lane (2 FMNMX; movs are virtual)
__device__ __forceinline__ ULL relu2(ULL s) {
    return pack2(fmaxf(f_lo(s), 0.f), fmaxf(f_hi(s), 0.f));
}

// ---------------------------------------------------------------------------
// Projection kernel: C = A * B^T, k-pair packed, 32x64 tile, 256 thr,
// per-thread 4 rows x 2 cols.  Grid (64,1,4).  (R13-proven mainloop.)
// z: 0,1 = dec (b=0,1) -> g_dprojT (transposed store) ; 2,3 = enc -> g_eprojT
// ---------------------------------------------------------------------------
__global__ __launch_bounds__(256) void proj_kernel(
    const float* __restrict__ dec, const float* __restrict__ enc,
    const float* __restrict__ Wm,  const float* __restrict__ bm,
    const float* __restrict__ wo)
{
    __shared__ __align__(16) ULL AsP[32*17];   // [row][kpair], stride 17
    __shared__ __align__(16) ULL BsP[16*66];   // [kpair][col], stride 66

    const int tx = threadIdx.x;                // 0..31
    const int ty = threadIdx.y;                // 0..7
    const int t  = ty*32 + tx;
    const int typ = blockIdx.z >> 1;
    const int b   = blockIdx.z & 1;
    const int bx  = blockIdx.x;

    int row0, col0;
    const float *Ap, *Bp;
    int lda, ldb;
    if (typ == 0) {                            // dec: rows=q (16 tiles), cols=d (4 tiles)
        row0 = (bx >> 2) * 32; col0 = (bx & 3) * 64;
        Ap = dec + (size_t)b*SEQ*HD + (size_t)row0*HD;  lda = HD;
        Bp = Wm + HD + (size_t)col0*(2*HD);             ldb = 2*HD;   // Wd[d][k]
    } else {                                   // enc: rows=d (8 tiles), cols=e (8 tiles)
        row0 = (bx >> 3) * 32; col0 = (bx & 7) * 64;
        Ap = Wm + (size_t)row0*(2*HD);                  lda = 2*HD;   // We[d][k]
        Bp = enc + (size_t)b*SEQ*HD + (size_t)col0*HD;  ldb = HD;
    }

    ULL acc[4][2];
    #pragma unroll
    for (int i=0;i<4;i++){ acc[i][0]=0ULL; acc[i][1]=0ULL; }

    const int ar = t >> 3, akg = t & 7;        // A: 32 rows x 8 f4-groups

    for (int c = 0; c < 8; c++) {
        __syncthreads();
        {   // stage A (k-pairs, natural order)
            float4 av = *(const float4*)(Ap + (size_t)ar*lda + c*32 + akg*4);
            float2* pa = (float2*)&AsP[ar*17 + akg*2];
            pa[0] = make_float2(av.x, av.y);
            pa[1] = make_float2(av.z, av.w);
        }
        #pragma unroll
        for (int r = 0; r < 2; r++) {          // stage B transposed to [kpair][col]
            int f4i = t + r*256;
            int bc = f4i >> 3, bkg = f4i & 7;
            float4 bv = *(const float4*)(Bp + (size_t)bc*ldb + c*32 + bkg*4);
            *(float2*)&BsP[(bkg*2+0)*66 + bc] = make_float2(bv.x, bv.y);
            *(float2*)&BsP[(bkg*2+1)*66 + bc] = make_float2(bv.z, bv.w);
        }
        __syncthreads();
        #pragma unroll
        for (int kk = 0; kk < 16; kk++) {
            ULL a2[4];
            #pragma unroll
            for (int i=0;i<4;i++) a2[i] = AsP[(4*ty+i)*17 + kk];
            ulonglong2 b2 = *(const ulonglong2*)&BsP[kk*66 + 2*tx];  // LDS.128
            #pragma unroll
            for (int i=0;i<4;i++){
                acc[i][0] = fma2(a2[i], b2.x, acc[i][0]);
                acc[i][1] = fma2(a2[i], b2.y, acc[i][1]);
            }
        }
    }

    if (typ == 0) {
        const int d0 = col0 + 2*tx;
        const float aw0 = fabsf(wo[d0]), aw1 = fabsf(wo[d0+1]);
        const float m0  = bm[d0],        m1  = bm[d0+1];
        float* C0 = g_dprojT + ((size_t)b*HD + d0)*SEQ;   // row d0
        float* C1 = C0 + SEQ;                             // row d0+1
        #pragma unroll
        for (int i=0;i<4;i++) {
            int q = row0 + 4*ty + i;
            float sx = f_lo(acc[i][0]) + f_hi(acc[i][0]);
            float sy = f_lo(acc[i][1]) + f_hi(acc[i][1]);
            C0[q] = (sx + m0)*aw0;
            C1[q] = (sy + m1)*aw1;
        }
    } else {
        const int e0 = col0 + 2*tx;
        float* Cp = g_eprojT + (size_t)b*HD*SEQ;
        #pragma unroll
        for (int i=0;i<4;i++) {
            int d = row0 + 4*ty + i;
            float aw = fabsf(wo[d]);
            float sx = f_lo(acc[i][0]) + f_hi(acc[i][0]);
            float sy = f_lo(acc[i][1]) + f_hi(acc[i][1]);
            *(float2*)(Cp + (size_t)d*SEQ + e0) = make_float2(sx*aw, sy*aw);
        }
    }
}

// ---------------------------------------------------------------------------
// Main pairwise kernel — d split across lanes, e in registers.
// CTA: 256 thr (8 warps), tile 16q x 32e.  Warp (wy=w>>1, wx=w&1): 4q x 16e.
// Lane owns d = 32c + lane (8 d's).  Accs: 32 f32x2 (4q x 8 e-pairs).
// u: LDG.128 from g_dprojT[d][q0..q0+3] (prefetched).  sg: from wo[d].
// v: 4x LDS.128 per d from Vt[d][e-slice] (staged once; stride 36 -> no
// conflicts).  NO syncs in mainloop, NO broadcast LDS.
// End: 5-step butterfly shfl reduce over lanes; lane l holds site l
// (q = l>>3, ep = l&7).  Grid (16,32,2) = 1024 CTAs = 8192 warps.
// out[b,q,e] = sum_d sgn(w_d)*relu(u+v) + bo
// ---------------------------------------------------------------------------
__global__ __launch_bounds__(256) void attn_kernel(
    const float* __restrict__ wo, const float* __restrict__ bo,
    float* __restrict__ out)
{
    __shared__ __align__(16) float Vt[256*36];  // [d][e-slice 32], stride 36

    const int t    = threadIdx.x;               // 0..255 (flat)
    const int lane = t & 31;
    const int warp = t >> 5;
    const int wy   = warp >> 1;                 // 0..3  (q-group)
    const int wx   = warp & 1;                  // 0..1  (e-half)
    const int et = blockIdx.x, qt = blockIdx.y, b = blockIdx.z;

    // ---- stage Vt: 256 d x 32 e, once ----
    const float* Vsrc = g_eprojT + (size_t)b*HD*SEQ + et*32;
    #pragma unroll
    for (int j = 0; j < 8; j++) {
        int idx = j*256 + t;                    // 0..2047 float4s
        int d = idx >> 3, eq = idx & 7;
        *(float4*)&Vt[d*36 + eq*4] =
            *(const float4*)(Vsrc + (size_t)d*SEQ + eq*4);
    }
    __syncthreads();

    const int q0 = qt*16 + wy*4;
    const float* Usrc = g_dprojT + (size_t)b*HD*SEQ + q0;

    ULL A[32];
    #pragma unroll
    for (int i = 0; i < 32; i++) A[i] = 0ULL;

    // prefetch chunk 0
    float4 u4n = *(const float4*)(Usrc + (size_t)lane*SEQ);
    float  wn  = wo[lane];

    #pragma unroll 2
    for (int c = 0; c < 8; c++) {
        const int d = c*32 + lane;
        float4 u4 = u4n; float wv = wn;
        if (c < 7) {                            // prefetch next chunk
            int dn = d + 32;
            u4n = *(const float4*)(Usrc + (size_t)dn*SEQ);
            wn  = wo[dn];
        }
        const float sg = copysignf(1.f, wv);
        const ULL sg2 = pack2(sg, sg);
        ULL ud[4];
        ud[0] = pack2(u4.x, u4.x); ud[1] = pack2(u4.y, u4.y);
        ud[2] = pack2(u4.z, u4.z); ud[3] = pack2(u4.w, u4.w);
        const float* Vrow = &Vt[d*36 + wx*16];
        #pragma unroll
        for (int eq = 0; eq < 4; eq++) {
            ulonglong2 vp = *(const ulonglong2*)(Vrow + eq*4);   // 2 e-pairs
            #pragma unroll
            for (int k = 0; k < 4; k++) {
                A[k*8 + eq*2    ] = fma2(relu2(add2(ud[k], vp.x)), sg2, A[k*8 + eq*2    ]);
                A[k*8 + eq*2 + 1] = fma2(relu2(add2(ud[k], vp.y)), sg2, A[k*8 + eq*2 + 1]);
            }
        }
    }

    // ---- butterfly reduce across lanes (in-place, value-selects only) ----
    // After step K: lanes with bit=0 hold lower-index sums, bit=1 upper.
    // Final: lane l holds original site index l, summed over all 32 lanes.
#define RSTEP(K)                                                           \
    {                                                                      \
        const bool bb = (lane & (K)) != 0;                                 \
        _Pragma("unroll")                                                  \
        for (int i = 0; i < (K); i++) {                                    \
            ULL lo = A[i], hi = A[i + (K)];                                \
            ULL keep = bb ? hi : lo;                                       \
            ULL send = bb ? lo : hi;                                       \
            ULL got  = __shfl_xor_sync(0xFFFFFFFFu, send, (K));            \
            A[i] = add2(keep, got);                                        \
        }                                                                  \
    }
    RSTEP(16) RSTEP(8) RSTEP(4) RSTEP(2) RSTEP(1)
#undef RSTEP

    const float bov = bo[0];
    const int qq = lane >> 3, ep = lane & 7;    // site l -> (q, e-pair)
    float* O = out + ((size_t)b*SEQ + q0 + qq)*SEQ + et*32 + wx*16 + ep*2;
    *(float2*)O = make_float2(f_lo(A[0]) + bov, f_hi(A[0]) + bov);
}

extern "C" void kernel_launch(void* const* d_in, const int* in_sizes, int n_in,
                              void* d_out, int out_size)
{
    const float* dec = (const float*)d_in[0];
    const float* enc = (const float*)d_in[1];
    const float* Wm  = (const float*)d_in[2];
    const float* bm  = (const float*)d_in[3];
    const float* wo  = (const float*)d_in[4];
    const float* bo  = (const float*)d_in[5];
    float* out = (float*)d_out;

    proj_kernel<<<dim3(64,1,4), dim3(32,8)>>>(dec, enc, Wm, bm, wo);
    attn_kernel<<<dim3(16,32,2), dim3(256,1,1)>>>(wo, bo, out);
}